// round 8
// baseline (speedup 1.0000x reference)
#include <cuda_runtime.h>
#include <cuda_bf16.h>

#define NN 10000
#define EE 100000
#define W  32
#define KW 128

// ---------------- scratch (static __device__, allocation-free) ----------------
__device__ float g_h[NN * W];          // node features
__device__ float g_coord[NN * 3];      // coords (updated per depth)
__device__ float g_p1[EE * 64];        // edge MLP layer-1 partial (edge_attr part, depth-invariant)
__device__ float g_k2[EE * KW];        // edge MLP layer-2 output (per depth)
__device__ float g_G[(size_t)NN * 4096];  // per-node contracted kernel G[n, c*32+i]  (164MB)
__device__ float g_W3p[32 * 4096];     // permuted ker_w3: W3p[j, c*32+i] = ker_w3[c, i*32+j]
__device__ float g_Bh[NN * W];         // bias term Bh[n,i] = sum_j b3[i*32+j] h[n,j]
__device__ float g_msum[NN * W];       // segment sums
__device__ float g_csum[NN * 3];
__device__ float g_deg[NN];            // in-degree of 'row' (constant over depth)

// ---------------- kernels ----------------

__global__ void k_init(const float* __restrict__ x, const float* __restrict__ coords,
                       const float* __restrict__ fc1w, const float* __restrict__ fc1b, int n) {
    int idx = blockIdx.x * blockDim.x + threadIdx.x;
    if (idx < n * W) {
        int node = idx >> 5, i = idx & 31;
        float acc = fc1b[i];
#pragma unroll
        for (int j = 0; j < 3; j++) acc += x[node * 3 + j] * fc1w[j * W + i];
        g_h[idx] = acc;
    }
    if (idx < n * 3) g_coord[idx] = coords[idx];
}

// permute ker_w3 [128,1024] (q = i*32+j) -> W3p [32,4096] (col = c*32+i)
__global__ void k_w3p(const float* __restrict__ kw3) {
    int idx = blockIdx.x * blockDim.x + threadIdx.x;
    if (idx < 128 * 1024) {
        int c = idx >> 10, rem = idx & 1023, i = rem >> 5, j = rem & 31;
        g_W3p[j * 4096 + c * 32 + i] = kw3[idx];
    }
}

// edge-attr part of kernel-MLP layer 1 (depth invariant)
__global__ void k_p1(const float* __restrict__ ea, const float* __restrict__ kw1,
                     const float* __restrict__ kb1, int e) {
    int idx = blockIdx.x * blockDim.x + threadIdx.x;
    if (idx >= e * 64) return;
    int ed = idx >> 6, c = idx & 63;
    float acc = kb1[c];
#pragma unroll
    for (int a = 0; a < 6; a++) acc += ea[ed * 6 + a] * kw1[a * 64 + c];
    g_p1[idx] = acc;
}

__global__ void k_zero_deg(int n) {
    int idx = blockIdx.x * blockDim.x + threadIdx.x;
    if (idx < n) g_deg[idx] = 0.0f;
}

__global__ void k_deg(const int* __restrict__ ei, int e) {
    int idx = blockIdx.x * blockDim.x + threadIdx.x;
    if (idx < e) atomicAdd(&g_deg[ei[idx]], 1.0f);
}

__global__ void k_zero_acc(int n) {
    int idx = blockIdx.x * blockDim.x + threadIdx.x;
    if (idx < n * W) g_msum[idx] = 0.0f;
    if (idx < n * 3) g_csum[idx] = 0.0f;
}

// per-depth: radial + kernel-MLP layers 1+2 -> g_k2[E,128]
__global__ __launch_bounds__(128) void k_edge_mlp(const int* __restrict__ ei,
                                                  const float* __restrict__ kw1,
                                                  const float* __restrict__ kw2,
                                                  const float* __restrict__ kb2, int e) {
    __shared__ float w2s[64 * KW];   // 32KB
    __shared__ float k1s[64];
    const int tid = threadIdx.x;
    for (int i = tid; i < 64 * KW; i += 128) w2s[i] = kw2[i];
    __syncthreads();
    int e0 = blockIdx.x * 16;
    for (int t = 0; t < 16; t++) {
        int ed = e0 + t;
        if (ed >= e) break;
        int r = ei[ed], c = ei[e + ed];
        if (tid < 64) {
            float rad = 0.0f;
#pragma unroll
            for (int d = 0; d < 3; d++) {
                float dd = g_coord[r * 3 + d] - g_coord[c * 3 + d];
                rad += dd * dd;
            }
            float v = g_p1[ed * 64 + tid] + rad * kw1[6 * 64 + tid];
            k1s[tid] = fmaxf(v, 0.0f);
        }
        __syncthreads();
        float acc = kb2[tid];
#pragma unroll
        for (int cc = 0; cc < 64; cc++) acc += k1s[cc] * w2s[cc * KW + tid];
        g_k2[(size_t)ed * KW + tid] = fmaxf(acc, 0.0f);
        __syncthreads();
    }
}

// per-depth GEMM: G[n, 0:4096] = h[n, 0:32] @ W3p[32, 4096]
// tile: 64 nodes x 128 cols per block, 256 threads, each thread 8x4 outputs
__global__ __launch_bounds__(256) void k_G(int n) {
    __shared__ float hs[64 * 32];    // 8KB
    __shared__ float bs[32 * 128];   // 16KB
    const int tid = threadIdx.x;
    const int n0 = blockIdx.x * 64;
    const int q0 = blockIdx.y * 128;
    for (int i = tid; i < 64 * 32; i += 256) {
        int nn = i >> 5, j = i & 31;
        int node = n0 + nn;
        hs[i] = (node < n) ? g_h[node * 32 + j] : 0.0f;
    }
    for (int i = tid; i < 32 * 128; i += 256) {
        int j = i >> 7, q = i & 127;
        bs[i] = g_W3p[j * 4096 + q0 + q];
    }
    __syncthreads();
    const int ty = tid >> 5, tx = tid & 31;
    float acc[8][4];
#pragma unroll
    for (int r = 0; r < 8; r++)
#pragma unroll
        for (int s = 0; s < 4; s++) acc[r][s] = 0.0f;
#pragma unroll
    for (int j = 0; j < 32; j++) {
        float a[8], b[4];
#pragma unroll
        for (int r = 0; r < 8; r++) a[r] = hs[(ty + 8 * r) * 32 + j];
#pragma unroll
        for (int s = 0; s < 4; s++) b[s] = bs[j * 128 + tx + 32 * s];
#pragma unroll
        for (int r = 0; r < 8; r++)
#pragma unroll
            for (int s = 0; s < 4; s++) acc[r][s] += a[r] * b[s];
    }
#pragma unroll
    for (int r = 0; r < 8; r++) {
        int node = n0 + ty + 8 * r;
        if (node < n) {
#pragma unroll
            for (int s = 0; s < 4; s++)
                g_G[(size_t)node * 4096 + q0 + tx + 32 * s] = acc[r][s];
        }
    }
}

// per-depth: Bh[n,i] = sum_j ker_b3[i*32+j] * h[n,j]
__global__ void k_Bh(const float* __restrict__ kb3, int n) {
    int idx = blockIdx.x * blockDim.x + threadIdx.x;
    if (idx >= n * W) return;
    int node = idx >> 5, i = idx & 31;
    float acc = 0.0f;
#pragma unroll
    for (int j = 0; j < 32; j++) acc += kb3[i * 32 + j] * g_h[node * 32 + j];
    g_Bh[idx] = acc;
}

// per-depth fused: m[e] = k2[e] @ G[col] + Bh[col]; phi; atomic scatter to msum/csum
__global__ __launch_bounds__(256) void k_edge_m(const int* __restrict__ ei,
                                                const float* __restrict__ cmw1,
                                                const float* __restrict__ cmb1,
                                                const float* __restrict__ cmw2, int e) {
    int gw = (blockIdx.x * blockDim.x + threadIdx.x) >> 5;
    int lane = threadIdx.x & 31;
    if (gw >= e) return;
    const int ed = gw;
    const int r = ei[ed], c = ei[e + ed];

    float kreg[4];
#pragma unroll
    for (int t = 0; t < 4; t++) kreg[t] = g_k2[(size_t)ed * 128 + t * 32 + lane];

    const float* gb = g_G + (size_t)c * 4096;
    float a0 = g_Bh[c * 32 + lane], a1 = 0.f, a2 = 0.f, a3 = 0.f;
#pragma unroll
    for (int l = 0; l < 32; l++) {
        float k0 = __shfl_sync(0xffffffffu, kreg[0], l);
        float k1 = __shfl_sync(0xffffffffu, kreg[1], l);
        float k2v = __shfl_sync(0xffffffffu, kreg[2], l);
        float k3 = __shfl_sync(0xffffffffu, kreg[3], l);
        a0 += k0 * gb[(l) * 32 + lane];
        a1 += k1 * gb[(32 + l) * 32 + lane];
        a2 += k2v * gb[(64 + l) * 32 + lane];
        a3 += k3 * gb[(96 + l) * 32 + lane];
    }
    float m = (a0 + a1) + (a2 + a3);

    // phi = relu(m @ cm_w1 + cm_b1) @ cm_w2
    float tac = cmb1[lane];
#pragma unroll
    for (int i = 0; i < 32; i++)
        tac += __shfl_sync(0xffffffffu, m, i) * cmw1[i * 32 + lane];
    tac = fmaxf(tac, 0.0f);
    float ph = tac * cmw2[lane];
#pragma unroll
    for (int o = 16; o; o >>= 1) ph += __shfl_xor_sync(0xffffffffu, ph, o);

    atomicAdd(&g_msum[r * 32 + lane], m);
    if (lane < 3) {
        float cd = g_coord[r * 3 + lane] - g_coord[c * 3 + lane];
        atomicAdd(&g_csum[r * 3 + lane], cd * ph);
    }
}

// per-depth: h = relu(h + msum/deg); coord += csum/deg
__global__ void k_update(int n) {
    int idx = blockIdx.x * blockDim.x + threadIdx.x;
    if (idx >= n * W) return;
    int node = idx >> 5, i = idx & 31;
    float inv = 1.0f / fmaxf(g_deg[node], 1.0f);
    g_h[idx] = fmaxf(g_h[idx] + g_msum[idx] * inv, 0.0f);
    if (i < 3) g_coord[node * 3 + i] += g_csum[node * 3 + i] * inv;
}

// final head: out[n] = relu(h @ fc2_w1 + b1) @ fc2_w2 + b2 ; also write coord
__global__ __launch_bounds__(256) void k_out(const float* __restrict__ fw1,
                                              const float* __restrict__ fb1,
                                              const float* __restrict__ fw2,
                                              const float* __restrict__ fb2,
                                              float* __restrict__ dout, int n) {
    int gw = (blockIdx.x * blockDim.x + threadIdx.x) >> 5;
    int lane = threadIdx.x & 31;
    if (gw >= n) return;
    const int node = gw;
    float hm = g_h[node * 32 + lane];
    float t0 = fb1[lane], t1 = fb1[lane + 32];
#pragma unroll
    for (int i = 0; i < 32; i++) {
        float hh = __shfl_sync(0xffffffffu, hm, i);
        t0 += hh * fw1[i * 64 + lane];
        t1 += hh * fw1[i * 64 + lane + 32];
    }
    t0 = fmaxf(t0, 0.0f);
    t1 = fmaxf(t1, 0.0f);
    float part = t0 * fw2[lane] + t1 * fw2[32 + lane];
#pragma unroll
    for (int o = 16; o; o >>= 1) part += __shfl_xor_sync(0xffffffffu, part, o);
    if (lane == 0) dout[node] = part + fb2[0];
    if (lane < 3) dout[n + node * 3 + lane] = g_coord[node * 3 + lane];
}

// ---------------- host launcher ----------------
extern "C" void kernel_launch(void* const* d_in, const int* in_sizes, int n_in,
                              void* d_out, int out_size) {
    const float* x      = (const float*)d_in[0];
    const int*   ei     = (const int*)  d_in[1];
    const float* eattr  = (const float*)d_in[2];
    const float* coords = (const float*)d_in[3];
    const float* fc1w   = (const float*)d_in[4];
    const float* fc1b   = (const float*)d_in[5];
    const float* kw1    = (const float*)d_in[6];
    const float* kb1    = (const float*)d_in[7];
    const float* kw2    = (const float*)d_in[8];
    const float* kb2    = (const float*)d_in[9];
    const float* kw3    = (const float*)d_in[10];
    const float* kb3    = (const float*)d_in[11];
    const float* cmw1   = (const float*)d_in[12];
    const float* cmb1   = (const float*)d_in[13];
    const float* cmw2   = (const float*)d_in[14];
    const float* fw1    = (const float*)d_in[15];
    const float* fb1    = (const float*)d_in[16];
    const float* fw2    = (const float*)d_in[17];
    const float* fb2    = (const float*)d_in[18];
    float* dout = (float*)d_out;

    int n = in_sizes[0] / 3;   // 10000
    int e = in_sizes[1] / 2;   // 100000
    if (n > NN) n = NN;
    if (e > EE) e = EE;

    const int T = 256;
    int gn32 = (n * W + T - 1) / T;

    k_init<<<gn32, T>>>(x, coords, fc1w, fc1b, n);
    k_w3p<<<(128 * 1024 + T - 1) / T, T>>>(kw3);
    k_p1<<<(e * 64 + T - 1) / T, T>>>(eattr, kw1, kb1, e);
    k_zero_deg<<<(n + T - 1) / T, T>>>(n);
    k_deg<<<(e + T - 1) / T, T>>>(ei, e);

    dim3 gG((n + 63) / 64, 32);
    for (int depth = 0; depth < 3; depth++) {
        k_zero_acc<<<gn32, T>>>(n);
        k_edge_mlp<<<(e + 15) / 16, 128>>>(ei, kw1, kw2, kb2, e);
        k_G<<<gG, 256>>>(n);
        k_Bh<<<gn32, T>>>(kb3, n);
        k_edge_m<<<(e * 32 + T - 1) / T, T>>>(ei, cmw1, cmb1, cmw2, e);
        k_update<<<gn32, T>>>(n);
    }
    k_out<<<(n * 32 + T - 1) / T, T>>>(fw1, fb1, fw2, fb2, dout, n);
}

// round 9
// speedup vs baseline: 1.2369x; 1.2369x over previous
#include <cuda_runtime.h>
#include <cuda_bf16.h>

#define NN 10000
#define EE 100000
#define W  32
#define KW 128
#define NPB 8   // nodes per block in fused edge kernel

// ---------------- scratch (static __device__, allocation-free) ----------------
__device__ float g_h[NN * W];
__device__ float g_coord[NN * 3];
__device__ float g_G[(size_t)NN * 4096];   // transposed per-node kernel: G[n][i*128+c]
__device__ float g_W3p[32 * 4096];         // W3p[j][i*128+c] = ker_w3[c][i*32+j]
__device__ float g_Bh[NN * W];
__device__ float g_msum[NN * W];
__device__ float g_csum[NN * 3];
__device__ int   g_degi[NN];               // row in-degree
__device__ int   g_cnt[NN];                // col histogram
__device__ int   g_offs[NN + 1];           // col segment offsets
__device__ int   g_cur[NN];                // scatter cursor
__device__ int   g_srow[EE];               // row of sorted edges
__device__ float g_sea[EE * 6];            // permuted edge_attr

// ---------------- setup kernels ----------------

__global__ void k_init(const float* __restrict__ x, const float* __restrict__ coords,
                       const float* __restrict__ fc1w, const float* __restrict__ fc1b, int n) {
    int idx = blockIdx.x * blockDim.x + threadIdx.x;
    if (idx < n * W) {
        int node = idx >> 5, i = idx & 31;
        float acc = fc1b[i];
#pragma unroll
        for (int j = 0; j < 3; j++) acc += x[node * 3 + j] * fc1w[j * W + i];
        g_h[idx] = acc;
    }
    if (idx < n * 3) g_coord[idx] = coords[idx];
}

// ker_w3 [128,1024] (q = i*32+j) -> W3p[j][i*128+c]
__global__ void k_w3p(const float* __restrict__ kw3) {
    int idx = blockIdx.x * blockDim.x + threadIdx.x;
    if (idx < 128 * 1024) {
        int c = idx >> 10, rem = idx & 1023, i = rem >> 5, j = rem & 31;
        g_W3p[j * 4096 + i * 128 + c] = kw3[idx];
    }
}

__global__ void k_zero_hist(int n) {
    int idx = blockIdx.x * blockDim.x + threadIdx.x;
    if (idx < n) { g_cnt[idx] = 0; g_degi[idx] = 0; }
}

__global__ void k_hist(const int* __restrict__ ei, int e) {
    int idx = blockIdx.x * blockDim.x + threadIdx.x;
    if (idx < e) {
        atomicAdd(&g_cnt[ei[e + idx]], 1);
        atomicAdd(&g_degi[ei[idx]], 1);
    }
}

// single-block exclusive scan of g_cnt[0..n) -> g_offs, g_cur
__global__ __launch_bounds__(1024) void k_scan(int n) {
    __shared__ int ts[1024];
    int tid = threadIdx.x;
    int per = (n + 1023) / 1024;
    int base = tid * per;
    int s = 0;
    for (int i = 0; i < per; i++) { int idx = base + i; if (idx < n) s += g_cnt[idx]; }
    ts[tid] = s;
    __syncthreads();
    for (int off = 1; off < 1024; off <<= 1) {
        int v = (tid >= off) ? ts[tid - off] : 0;
        __syncthreads();
        ts[tid] += v;
        __syncthreads();
    }
    int run = (tid > 0) ? ts[tid - 1] : 0;
    for (int i = 0; i < per; i++) {
        int idx = base + i;
        if (idx < n) { int cv = g_cnt[idx]; g_offs[idx] = run; g_cur[idx] = run; run += cv; }
    }
    if (tid == 1023) g_offs[n] = run;
}

__global__ void k_scatter(const int* __restrict__ ei, const float* __restrict__ ea, int e) {
    int idx = blockIdx.x * blockDim.x + threadIdx.x;
    if (idx >= e) return;
    int c = ei[e + idx];
    int p = atomicAdd(&g_cur[c], 1);
    g_srow[p] = ei[idx];
#pragma unroll
    for (int a = 0; a < 6; a++) g_sea[p * 6 + a] = ea[idx * 6 + a];
}

__global__ void k_zero_acc(int n) {
    int idx = blockIdx.x * blockDim.x + threadIdx.x;
    if (idx < n * W) g_msum[idx] = 0.0f;
    if (idx < n * 3) g_csum[idx] = 0.0f;
}

// ---------------- per-depth kernels ----------------

// G[n][i*128+c] = sum_j h[n][j] * W3p[j][i*128+c]; 64 nodes x 128 cols per block
__global__ __launch_bounds__(256) void k_G(int n) {
    __shared__ float hs[64 * 32];
    __shared__ float bs[32 * 128];
    const int tid = threadIdx.x;
    const int n0 = blockIdx.x * 64;
    const int q0 = blockIdx.y * 128;
    for (int i = tid; i < 64 * 32; i += 256) {
        int nn = i >> 5, j = i & 31;
        int node = n0 + nn;
        hs[i] = (node < n) ? g_h[node * 32 + j] : 0.0f;
    }
    for (int i = tid; i < 32 * 128; i += 256) {
        int j = i >> 7, q = i & 127;
        bs[i] = g_W3p[j * 4096 + q0 + q];
    }
    __syncthreads();
    const int ty = tid >> 5, tx = tid & 31;
    float4 acc[8];
#pragma unroll
    for (int r = 0; r < 8; r++) acc[r] = make_float4(0.f, 0.f, 0.f, 0.f);
#pragma unroll
    for (int j = 0; j < 32; j++) {
        float4 bv = *(const float4*)&bs[j * 128 + tx * 4];
#pragma unroll
        for (int r = 0; r < 8; r++) {
            float a = hs[(ty + 8 * r) * 32 + j];
            acc[r].x += a * bv.x; acc[r].y += a * bv.y;
            acc[r].z += a * bv.z; acc[r].w += a * bv.w;
        }
    }
#pragma unroll
    for (int r = 0; r < 8; r++) {
        int node = n0 + ty + 8 * r;
        if (node < n)
            *(float4*)&g_G[(size_t)node * 4096 + q0 + tx * 4] = acc[r];
    }
}

__global__ void k_Bh(const float* __restrict__ kb3, int n) {
    int idx = blockIdx.x * blockDim.x + threadIdx.x;
    if (idx >= n * W) return;
    int node = idx >> 5, i = idx & 31;
    float acc = 0.0f;
#pragma unroll
    for (int j = 0; j < 32; j++) acc += kb3[i * 32 + j] * g_h[node * 32 + j];
    g_Bh[idx] = acc;
}

// smem layout offsets (floats)
#define SM_W2P   0        // 64*128 permuted [cc][lane*4+t]
#define SM_KW1   8192     // 7*64
#define SM_KB1   8640     // 64
#define SM_KB2   8704     // 128
#define SM_CMW1  8832     // 32*32
#define SM_CMB1  9856     // 32
#define SM_CMW2  9888     // 32
#define SM_GS    9920     // 32*132 (padded)
#define SM_K2S   14144    // 8*128
#define SM_K1S   15168    // 8*64
#define SM_MS    15680    // 8*32
#define SM_TOTAL 15936    // floats -> 63744 bytes

// fused per-depth edge kernel: block owns NPB col-nodes; G[v] cached in smem
__global__ __launch_bounds__(256) void k_edge(const float* __restrict__ kw1,
                                              const float* __restrict__ kb1,
                                              const float* __restrict__ kw2,
                                              const float* __restrict__ kb2,
                                              const float* __restrict__ cmw1,
                                              const float* __restrict__ cmb1,
                                              const float* __restrict__ cmw2,
                                              int n) {
    extern __shared__ float sm[];
    const int tid = threadIdx.x, w = tid >> 5, lane = tid & 31;

    // stage weights (permute kw2 for float4 access)
    for (int i = tid; i < 8192; i += 256) {
        int cc = i >> 7, out = i & 127, t = out >> 5, ln = out & 31;
        sm[SM_W2P + cc * 128 + ln * 4 + t] = kw2[i];
    }
    for (int i = tid; i < 448; i += 256) sm[SM_KW1 + i] = kw1[i];
    if (tid < 64)  sm[SM_KB1 + tid] = kb1[tid];
    if (tid < 128) sm[SM_KB2 + tid] = kb2[tid];
    for (int i = tid; i < 1024; i += 256) sm[SM_CMW1 + i] = cmw1[i];
    if (tid < 32) { sm[SM_CMB1 + tid] = cmb1[tid]; sm[SM_CMW2 + tid] = cmw2[tid]; }

    int v0 = blockIdx.x * NPB;
    int v1 = v0 + NPB; if (v1 > n) v1 = n;
    for (int v = v0; v < v1; v++) {
        __syncthreads();
        // load G[v] into padded smem rows [i][132]
        for (int q = tid * 4; q < 4096; q += 1024) {
            int i = q >> 7, c = q & 127;
            *(float4*)&sm[SM_GS + i * 132 + c] = *(const float4*)&g_G[(size_t)v * 4096 + q];
        }
        __syncthreads();
        float bh = g_Bh[v * 32 + lane];
        float ccrd = (lane < 3) ? g_coord[v * 3 + lane] : 0.0f;
        int s0 = g_offs[v], s1 = g_offs[v + 1];
        for (int ed = s0 + w; ed < s1; ed += NPB) {
            int r = g_srow[ed];
            float cdl = (lane < 3) ? (g_coord[r * 3 + lane] - ccrd) : 0.0f;
            float d0 = __shfl_sync(0xffffffffu, cdl, 0);
            float d1 = __shfl_sync(0xffffffffu, cdl, 1);
            float d2 = __shfl_sync(0xffffffffu, cdl, 2);
            float rad = d0 * d0 + d1 * d1 + d2 * d2;

            // kernel-MLP layer 1 (each lane computes c=lane and c=lane+32)
            float k1a = sm[SM_KB1 + lane], k1b = sm[SM_KB1 + lane + 32];
#pragma unroll
            for (int a = 0; a < 6; a++) {
                float sa = g_sea[ed * 6 + a];
                k1a += sa * sm[SM_KW1 + a * 64 + lane];
                k1b += sa * sm[SM_KW1 + a * 64 + lane + 32];
            }
            k1a += rad * sm[SM_KW1 + 384 + lane];
            k1b += rad * sm[SM_KW1 + 384 + lane + 32];
            sm[SM_K1S + w * 64 + lane]      = fmaxf(k1a, 0.0f);
            sm[SM_K1S + w * 64 + lane + 32] = fmaxf(k1b, 0.0f);
            __syncwarp();

            // layer 2: k2[t*32+lane]
            float acc0 = sm[SM_KB2 + lane],      acc1 = sm[SM_KB2 + 32 + lane];
            float acc2 = sm[SM_KB2 + 64 + lane], acc3 = sm[SM_KB2 + 96 + lane];
#pragma unroll
            for (int cc = 0; cc < 64; cc += 4) {
                float4 kv = *(float4*)&sm[SM_K1S + w * 64 + cc];
                float4 w0 = *(float4*)&sm[SM_W2P + (cc + 0) * 128 + lane * 4];
                acc0 += kv.x * w0.x; acc1 += kv.x * w0.y; acc2 += kv.x * w0.z; acc3 += kv.x * w0.w;
                float4 w1 = *(float4*)&sm[SM_W2P + (cc + 1) * 128 + lane * 4];
                acc0 += kv.y * w1.x; acc1 += kv.y * w1.y; acc2 += kv.y * w1.z; acc3 += kv.y * w1.w;
                float4 w2v = *(float4*)&sm[SM_W2P + (cc + 2) * 128 + lane * 4];
                acc0 += kv.z * w2v.x; acc1 += kv.z * w2v.y; acc2 += kv.z * w2v.z; acc3 += kv.z * w2v.w;
                float4 w3v = *(float4*)&sm[SM_W2P + (cc + 3) * 128 + lane * 4];
                acc0 += kv.w * w3v.x; acc1 += kv.w * w3v.y; acc2 += kv.w * w3v.z; acc3 += kv.w * w3v.w;
            }
            __syncwarp();
            sm[SM_K2S + w * 128 + lane]      = fmaxf(acc0, 0.0f);
            sm[SM_K2S + w * 128 + 32 + lane] = fmaxf(acc1, 0.0f);
            sm[SM_K2S + w * 128 + 64 + lane] = fmaxf(acc2, 0.0f);
            sm[SM_K2S + w * 128 + 96 + lane] = fmaxf(acc3, 0.0f);
            __syncwarp();

            // contraction: m[lane] = bh + sum_c k2[c] * G[lane][c]
            float m = bh;
#pragma unroll
            for (int c4 = 0; c4 < 128; c4 += 4) {
                float4 kv = *(float4*)&sm[SM_K2S + w * 128 + c4];
                float4 gv = *(float4*)&sm[SM_GS + lane * 132 + c4];
                m += kv.x * gv.x + kv.y * gv.y + kv.z * gv.z + kv.w * gv.w;
            }
            __syncwarp();
            sm[SM_MS + w * 32 + lane] = m;
            __syncwarp();

            // phi = relu(m @ cm_w1 + cm_b1) @ cm_w2
            float tac = sm[SM_CMB1 + lane];
#pragma unroll
            for (int i = 0; i < 32; i += 4) {
                float4 mv = *(float4*)&sm[SM_MS + w * 32 + i];
                tac += mv.x * sm[SM_CMW1 + (i + 0) * 32 + lane];
                tac += mv.y * sm[SM_CMW1 + (i + 1) * 32 + lane];
                tac += mv.z * sm[SM_CMW1 + (i + 2) * 32 + lane];
                tac += mv.w * sm[SM_CMW1 + (i + 3) * 32 + lane];
            }
            tac = fmaxf(tac, 0.0f);
            float ph = tac * sm[SM_CMW2 + lane];
#pragma unroll
            for (int o = 16; o; o >>= 1) ph += __shfl_xor_sync(0xffffffffu, ph, o);

            atomicAdd(&g_msum[r * 32 + lane], m);
            if (lane < 3) atomicAdd(&g_csum[r * 3 + lane], cdl * ph);
            __syncwarp();
        }
    }
}

__global__ void k_update(int n) {
    int idx = blockIdx.x * blockDim.x + threadIdx.x;
    if (idx >= n * W) return;
    int node = idx >> 5, i = idx & 31;
    int d = g_degi[node];
    float inv = 1.0f / (float)(d > 1 ? d : 1);
    g_h[idx] = fmaxf(g_h[idx] + g_msum[idx] * inv, 0.0f);
    if (i < 3) g_coord[node * 3 + i] += g_csum[node * 3 + i] * inv;
}

__global__ __launch_bounds__(256) void k_out(const float* __restrict__ fw1,
                                             const float* __restrict__ fb1,
                                             const float* __restrict__ fw2,
                                             const float* __restrict__ fb2,
                                             float* __restrict__ dout, int n) {
    int gw = (blockIdx.x * blockDim.x + threadIdx.x) >> 5;
    int lane = threadIdx.x & 31;
    if (gw >= n) return;
    const int node = gw;
    float hm = g_h[node * 32 + lane];
    float t0 = fb1[lane], t1 = fb1[lane + 32];
#pragma unroll
    for (int i = 0; i < 32; i++) {
        float hh = __shfl_sync(0xffffffffu, hm, i);
        t0 += hh * fw1[i * 64 + lane];
        t1 += hh * fw1[i * 64 + lane + 32];
    }
    t0 = fmaxf(t0, 0.0f);
    t1 = fmaxf(t1, 0.0f);
    float part = t0 * fw2[lane] + t1 * fw2[32 + lane];
#pragma unroll
    for (int o = 16; o; o >>= 1) part += __shfl_xor_sync(0xffffffffu, part, o);
    if (lane == 0) dout[node] = part + fb2[0];
    if (lane < 3) dout[n + node * 3 + lane] = g_coord[node * 3 + lane];
}

// ---------------- host launcher ----------------
extern "C" void kernel_launch(void* const* d_in, const int* in_sizes, int n_in,
                              void* d_out, int out_size) {
    const float* x      = (const float*)d_in[0];
    const int*   ei     = (const int*)  d_in[1];
    const float* eattr  = (const float*)d_in[2];
    const float* coords = (const float*)d_in[3];
    const float* fc1w   = (const float*)d_in[4];
    const float* fc1b   = (const float*)d_in[5];
    const float* kw1    = (const float*)d_in[6];
    const float* kb1    = (const float*)d_in[7];
    const float* kw2    = (const float*)d_in[8];
    const float* kb2    = (const float*)d_in[9];
    const float* kw3    = (const float*)d_in[10];
    const float* kb3    = (const float*)d_in[11];
    const float* cmw1   = (const float*)d_in[12];
    const float* cmb1   = (const float*)d_in[13];
    const float* cmw2   = (const float*)d_in[14];
    const float* fw1    = (const float*)d_in[15];
    const float* fb1    = (const float*)d_in[16];
    const float* fw2    = (const float*)d_in[17];
    const float* fb2    = (const float*)d_in[18];
    float* dout = (float*)d_out;

    int n = in_sizes[0] / 3;   // 10000
    int e = in_sizes[1] / 2;   // 100000
    if (n > NN) n = NN;
    if (e > EE) e = EE;

    const int T = 256;
    int gn32 = (n * W + T - 1) / T;
    size_t smem_edge = (size_t)SM_TOTAL * sizeof(float);
    cudaFuncSetAttribute(k_edge, cudaFuncAttributeMaxDynamicSharedMemorySize, (int)smem_edge);

    k_init<<<gn32, T>>>(x, coords, fc1w, fc1b, n);
    k_w3p<<<(128 * 1024 + T - 1) / T, T>>>(kw3);
    k_zero_hist<<<(n + T - 1) / T, T>>>(n);
    k_hist<<<(e + T - 1) / T, T>>>(ei, e);
    k_scan<<<1, 1024>>>(n);
    k_scatter<<<(e + T - 1) / T, T>>>(ei, eattr, e);

    dim3 gG((n + 63) / 64, 32);
    int gEdge = (n + NPB - 1) / NPB;
    for (int depth = 0; depth < 3; depth++) {
        k_zero_acc<<<gn32, T>>>(n);
        k_G<<<gG, 256>>>(n);
        k_Bh<<<gn32, T>>>(kb3, n);
        k_edge<<<gEdge, 256, smem_edge>>>(kw1, kb1, kw2, kb2, cmw1, cmb1, cmw2, n);
        k_update<<<gn32, T>>>(n);
    }
    k_out<<<(n * 32 + T - 1) / T, T>>>(fw1, fb1, fw2, fb2, dout, n);
}